// round 1
// baseline (speedup 1.0000x reference)
#include <cuda_runtime.h>
#include <math.h>

#define BATCH 16
#define SEQ   1024
#define DIM   512
#define NHEAD 8
#define DPH   64
#define NROWS (BATCH*SEQ)   // 16384

// Scratch (device globals: no allocation allowed in kernel_launch)
__device__ float g_q[NROWS*DIM];
__device__ float g_k[NROWS*DIM];
__device__ float g_v[NROWS*DIM];
__device__ float g_M[BATCH*NHEAD*DPH*DPH];   // c2 * sgn ⊙ (K^T V) per (b,h)
__device__ float g_cs[BATCH*NHEAD*DPH];      // c1 * colsum(V) per (b,h)

// ---------------------------------------------------------------------------
// GEMM: Y[n,j] = sum_d X[n,d] * W[j,d] + bias[j]
// X: [NROWS, 512] row-major, W: [512, 512] row-major. 128x128x16 tile, 8x8/thread.
// ---------------------------------------------------------------------------
__global__ __launch_bounds__(256) void gemm_xwT_kernel(
    const float* __restrict__ X, const float* __restrict__ W,
    const float* __restrict__ bias, float* __restrict__ Y)
{
    const int K = DIM;
    __shared__ float As[16][128];
    __shared__ float Bs[16][128];
    int bm = blockIdx.y * 128;
    int bn = blockIdx.x * 128;
    int tid = threadIdx.x;
    int tx = tid & 15;   // 0..15 along N
    int ty = tid >> 4;   // 0..15 along M
    int lr = tid >> 1;          // 0..127 row within tile
    int lc = (tid & 1) * 8;     // 0 or 8

    float acc[8][8];
#pragma unroll
    for (int i = 0; i < 8; i++)
#pragma unroll
        for (int j = 0; j < 8; j++) acc[i][j] = 0.f;

    const float* Xp = X + (size_t)(bm + lr) * K + lc;
    const float* Wp = W + (size_t)(bn + lr) * K + lc;

    for (int k0 = 0; k0 < K; k0 += 16) {
        float4 a0 = *(const float4*)(Xp + k0);
        float4 a1 = *(const float4*)(Xp + k0 + 4);
        float4 b0 = *(const float4*)(Wp + k0);
        float4 b1 = *(const float4*)(Wp + k0 + 4);
        As[lc+0][lr] = a0.x; As[lc+1][lr] = a0.y; As[lc+2][lr] = a0.z; As[lc+3][lr] = a0.w;
        As[lc+4][lr] = a1.x; As[lc+5][lr] = a1.y; As[lc+6][lr] = a1.z; As[lc+7][lr] = a1.w;
        Bs[lc+0][lr] = b0.x; Bs[lc+1][lr] = b0.y; Bs[lc+2][lr] = b0.z; Bs[lc+3][lr] = b0.w;
        Bs[lc+4][lr] = b1.x; Bs[lc+5][lr] = b1.y; Bs[lc+6][lr] = b1.z; Bs[lc+7][lr] = b1.w;
        __syncthreads();
#pragma unroll
        for (int k = 0; k < 16; k++) {
            float4 a04 = *(const float4*)&As[k][ty*8];
            float4 a14 = *(const float4*)&As[k][ty*8+4];
            float4 b04 = *(const float4*)&Bs[k][tx*8];
            float4 b14 = *(const float4*)&Bs[k][tx*8+4];
            float a[8] = {a04.x, a04.y, a04.z, a04.w, a14.x, a14.y, a14.z, a14.w};
            float b[8] = {b04.x, b04.y, b04.z, b04.w, b14.x, b14.y, b14.z, b14.w};
#pragma unroll
            for (int i = 0; i < 8; i++)
#pragma unroll
                for (int j = 0; j < 8; j++) acc[i][j] += a[i] * b[j];
        }
        __syncthreads();
    }

#pragma unroll
    for (int i = 0; i < 8; i++) {
        int row = bm + ty * 8 + i;
#pragma unroll
        for (int j = 0; j < 8; j += 4) {
            int col = bn + tx * 8 + j;
            float4 o;
            o.x = acc[i][j+0] + bias[col+0];
            o.y = acc[i][j+1] + bias[col+1];
            o.z = acc[i][j+2] + bias[col+2];
            o.w = acc[i][j+3] + bias[col+3];
            *(float4*)&Y[(size_t)row * DIM + col] = o;
        }
    }
}

// ---------------------------------------------------------------------------
// Lorentz transform (in place, one block per row of 512):
//  time = sigmoid(y0)*exp(ls) + 1.0001 ; rest *= sqrt((time^2-1)/max(sum rest^2,1e-8))
// ---------------------------------------------------------------------------
__global__ __launch_bounds__(128) void lorentz_transform_kernel(
    float* __restrict__ Y, const float* __restrict__ ls_p)
{
    int row = blockIdx.x;
    int tid = threadIdx.x;
    float* y = Y + (size_t)row * DIM;
    float4 xv = *(float4*)&y[tid * 4];
    float local = xv.x*xv.x + xv.y*xv.y + xv.z*xv.z + xv.w*xv.w;
    if (tid == 0) local -= xv.x * xv.x;   // exclude time slot from sumsq

#pragma unroll
    for (int o = 16; o > 0; o >>= 1) local += __shfl_down_sync(0xffffffffu, local, o);

    __shared__ float s_red[4];
    __shared__ float s_time, s_ssc;
    if ((tid & 31) == 0) s_red[tid >> 5] = local;
    __syncthreads();
    if (tid == 0) {
        float sumsq = s_red[0] + s_red[1] + s_red[2] + s_red[3];
        sumsq = fmaxf(sumsq, 1e-8f);
        float time = expf(*ls_p) / (1.f + expf(-xv.x)) + 1.0001f;
        s_time = time;
        s_ssc = sqrtf((time * time - 1.f) / sumsq);
    }
    __syncthreads();
    float ssc = s_ssc;
    xv.x *= ssc; xv.y *= ssc; xv.z *= ssc; xv.w *= ssc;
    if (tid == 0) xv.x = s_time;
    *(float4*)&y[tid * 4] = xv;
}

// ---------------------------------------------------------------------------
// Per (b,h): CS[d] = c1 * sum_s V[s,d]     with c1 = 2/as + ab
// ---------------------------------------------------------------------------
__global__ __launch_bounds__(64) void colsum_kernel(
    const float* __restrict__ Vb, float* __restrict__ CS,
    const float* __restrict__ as_p, const float* __restrict__ ab_p)
{
    int bh = blockIdx.x;
    int b = bh >> 3, h = bh & 7;
    int d = threadIdx.x;
    const float* vp = Vb + (size_t)b * SEQ * DIM + h * DPH + d;
    float a0 = 0.f, a1 = 0.f, a2 = 0.f, a3 = 0.f;
#pragma unroll 4
    for (int s = 0; s < SEQ; s += 4) {
        a0 += vp[(size_t)(s+0) * DIM];
        a1 += vp[(size_t)(s+1) * DIM];
        a2 += vp[(size_t)(s+2) * DIM];
        a3 += vp[(size_t)(s+3) * DIM];
    }
    float c1 = 2.f / as_p[0] + ab_p[0];
    CS[bh * DPH + d] = (a0 + a1 + a2 + a3) * c1;
}

// ---------------------------------------------------------------------------
// Per (b,h): M'[d1,d2] = c2 * sgn[d1] * sum_s K[s,d1]*V[s,d2]   (c2 = 2/as)
// One block per (b,h); 256 threads; 4x4 register tile; s tiled by 32.
// ---------------------------------------------------------------------------
__global__ __launch_bounds__(256) void kkv_kernel(
    const float* __restrict__ Kb, const float* __restrict__ Vb,
    float* __restrict__ M, const float* __restrict__ as_p)
{
    int bh = blockIdx.x;
    int b = bh >> 3, h = bh & 7;
    __shared__ float Ks[32][64];
    __shared__ float Vs[32][64];
    int tid = threadIdx.x;
    int d1b = (tid >> 4) * 4;
    int d2b = (tid & 15) * 4;
    int lr = tid >> 3;          // 0..31
    int lc = (tid & 7) * 8;     // 0..56 step 8
    float acc[4][4];
#pragma unroll
    for (int i = 0; i < 4; i++)
#pragma unroll
        for (int j = 0; j < 4; j++) acc[i][j] = 0.f;

    const float* kp = Kb + (size_t)b * SEQ * DIM + h * DPH;
    const float* vp = Vb + (size_t)b * SEQ * DIM + h * DPH;

    for (int s0 = 0; s0 < SEQ; s0 += 32) {
        float4 k0 = *(const float4*)(kp + (size_t)(s0+lr) * DIM + lc);
        float4 k1 = *(const float4*)(kp + (size_t)(s0+lr) * DIM + lc + 4);
        float4 v0 = *(const float4*)(vp + (size_t)(s0+lr) * DIM + lc);
        float4 v1 = *(const float4*)(vp + (size_t)(s0+lr) * DIM + lc + 4);
        __syncthreads();
        *(float4*)&Ks[lr][lc]   = k0; *(float4*)&Ks[lr][lc+4] = k1;
        *(float4*)&Vs[lr][lc]   = v0; *(float4*)&Vs[lr][lc+4] = v1;
        __syncthreads();
#pragma unroll
        for (int ss = 0; ss < 32; ss++) {
            float4 kv = *(const float4*)&Ks[ss][d1b];
            float4 vv = *(const float4*)&Vs[ss][d2b];
            float ka[4] = {kv.x, kv.y, kv.z, kv.w};
            float va[4] = {vv.x, vv.y, vv.z, vv.w};
#pragma unroll
            for (int i = 0; i < 4; i++)
#pragma unroll
                for (int j = 0; j < 4; j++) acc[i][j] += ka[i] * va[j];
        }
    }

    float c2 = 2.f / as_p[0];
    float* Mp = M + (size_t)bh * DPH * DPH;
#pragma unroll
    for (int i = 0; i < 4; i++) {
        float sg = (d1b + i == 0) ? -c2 : c2;
#pragma unroll
        for (int j = 0; j < 4; j++)
            Mp[(d1b + i) * DPH + d2b + j] = acc[i][j] * sg;
    }
}

// ---------------------------------------------------------------------------
// ave[s,d] = CS[d] + sum_{d'} Q[s,d'] * M'[d',d];  ctx = ave / sqrt(max(|sum sgn*ave^2|,1e-8))
// Output layout: Out[b, s, h*64+d]. Grid (B*H, S/32); 8 warps; 1 row/warp-iter.
// ---------------------------------------------------------------------------
__global__ __launch_bounds__(256) void ave_kernel(
    const float* __restrict__ Qb, const float* __restrict__ M,
    const float* __restrict__ CS, float* __restrict__ Out)
{
    int bh = blockIdx.x;
    int b = bh >> 3, h = bh & 7;
    int s0 = blockIdx.y * 32;
    int tid = threadIdx.x;
    int warp = tid >> 5, lane = tid & 31;

    __shared__ float Ms[64][64];
    {
        const float* Mp = M + (size_t)bh * DPH * DPH;
        float* Msf = &Ms[0][0];
        for (int i = tid * 4; i < 4096; i += 1024)
            *(float4*)&Msf[i] = *(const float4*)&Mp[i];
    }
    __syncthreads();

    float cs0 = CS[bh * DPH + lane];
    float cs1 = CS[bh * DPH + lane + 32];
    const float* qp = Qb + (size_t)b * SEQ * DIM + h * DPH;

    for (int r = warp; r < 32; r += 8) {
        int srow = s0 + r;
        const float* q = qp + (size_t)srow * DIM;
        float a0 = cs0, a1 = cs1;
#pragma unroll
        for (int dp = 0; dp < 64; dp++) {
            float qv = __ldg(&q[dp]);      // broadcast across warp
            a0 += qv * Ms[dp][lane];
            a1 += qv * Ms[dp][lane + 32];
        }
        // Lorentz inner product: sgn[0] = -1
        float contrib = a0 * a0 * ((lane == 0) ? -1.f : 1.f) + a1 * a1;
#pragma unroll
        for (int o = 16; o > 0; o >>= 1) contrib += __shfl_xor_sync(0xffffffffu, contrib, o);
        float inv = 1.f / sqrtf(fmaxf(fabsf(contrib), 1e-8f));
        size_t ob = ((size_t)b * SEQ + srow) * DIM + h * DPH;
        Out[ob + lane]      = a0 * inv;
        Out[ob + lane + 32] = a1 * inv;
    }
}

// ---------------------------------------------------------------------------
extern "C" void kernel_launch(void* const* d_in, const int* in_sizes, int n_in,
                              void* d_out, int out_size)
{
    const float* key   = (const float*)d_in[0];
    const float* value = (const float*)d_in[1];
    const float* query = (const float*)d_in[2];
    const float* Wq  = (const float*)d_in[3];
    const float* bq  = (const float*)d_in[4];
    const float* lsq = (const float*)d_in[5];
    const float* Wk  = (const float*)d_in[6];
    const float* bk  = (const float*)d_in[7];
    const float* lsk = (const float*)d_in[8];
    const float* Wv  = (const float*)d_in[9];
    const float* bv  = (const float*)d_in[10];
    const float* lsv = (const float*)d_in[11];
    const float* as_p = (const float*)d_in[12];
    const float* ab_p = (const float*)d_in[13];
    float* out = (float*)d_out;

    float *gq, *gk, *gv, *gM, *gcs;
    cudaGetSymbolAddress((void**)&gq,  g_q);
    cudaGetSymbolAddress((void**)&gk,  g_k);
    cudaGetSymbolAddress((void**)&gv,  g_v);
    cudaGetSymbolAddress((void**)&gM,  g_M);
    cudaGetSymbolAddress((void**)&gcs, g_cs);

    dim3 ggrid(DIM / 128, NROWS / 128);

    gemm_xwT_kernel<<<ggrid, 256>>>(query, Wq, bq, gq);
    gemm_xwT_kernel<<<ggrid, 256>>>(key,   Wk, bk, gk);
    gemm_xwT_kernel<<<ggrid, 256>>>(value, Wv, bv, gv);

    lorentz_transform_kernel<<<NROWS, 128>>>(gq, lsq);
    lorentz_transform_kernel<<<NROWS, 128>>>(gk, lsk);
    lorentz_transform_kernel<<<NROWS, 128>>>(gv, lsv);

    colsum_kernel<<<BATCH * NHEAD, 64>>>(gv, gcs, as_p, ab_p);
    kkv_kernel<<<BATCH * NHEAD, 256>>>(gk, gv, gM, as_p);

    dim3 agrid(BATCH * NHEAD, SEQ / 32);
    ave_kernel<<<agrid, 256>>>(gq, gM, gcs, out);
}

// round 4
// speedup vs baseline: 1.5871x; 1.5871x over previous
#include <cuda_runtime.h>
#include <cuda_bf16.h>
#include <cstdint>
#include <math.h>

#define BATCH 16
#define SEQ   1024
#define DIM   512
#define NHEAD 8
#define DPH   64
#define NROWS (BATCH*SEQ)   // 16384

// ---------------------------------------------------------------------------
// Scratch (device globals: no allocation allowed anywhere)
// ---------------------------------------------------------------------------
__device__ float g_qkv[3*NROWS*DIM];                 // GEMM outputs (q,k,v)
__device__ __nv_bfloat16 g_xhi[3*NROWS*DIM];
__device__ __nv_bfloat16 g_xlo[3*NROWS*DIM];
__device__ __nv_bfloat16 g_whi[3*DIM*DIM];
__device__ __nv_bfloat16 g_wlo[3*DIM*DIM];
__device__ float g_M[BATCH*NHEAD*DPH*DPH];
__device__ float g_cs[BATCH*NHEAD*DPH];

// ---------------------------------------------------------------------------
// Small PTX helpers (base-target sm_80+ features only: cp.async/ldmatrix/mma)
// ---------------------------------------------------------------------------
__device__ __forceinline__ uint32_t smem_u32(const void* p) {
    uint32_t a;
    asm("{ .reg .u64 t; cvta.to.shared.u64 t, %1; cvt.u32.u64 %0, t; }"
        : "=r"(a) : "l"(p));
    return a;
}
__device__ __forceinline__ void cp16(uint32_t s, const void* g) {
    asm volatile("cp.async.cg.shared.global [%0], [%1], 16;" :: "r"(s), "l"(g));
}
__device__ __forceinline__ void cp_commit() {
    asm volatile("cp.async.commit_group;" ::: "memory");
}
template <int N>
__device__ __forceinline__ void cp_wait() {
    asm volatile("cp.async.wait_group %0;" :: "n"(N) : "memory");
}
__device__ __forceinline__ void ldsm4(uint32_t* r, uint32_t addr) {
    asm volatile("ldmatrix.sync.aligned.m8n8.x4.shared.b16 {%0,%1,%2,%3}, [%4];"
                 : "=r"(r[0]), "=r"(r[1]), "=r"(r[2]), "=r"(r[3]) : "r"(addr));
}
__device__ __forceinline__ void mma16816(float* c, const uint32_t* a,
                                         uint32_t b0, uint32_t b1) {
    asm volatile(
        "mma.sync.aligned.m16n8k16.row.col.f32.bf16.bf16.f32 "
        "{%0,%1,%2,%3}, {%4,%5,%6,%7}, {%8,%9}, {%0,%1,%2,%3};"
        : "+f"(c[0]), "+f"(c[1]), "+f"(c[2]), "+f"(c[3])
        : "r"(a[0]), "r"(a[1]), "r"(a[2]), "r"(a[3]), "r"(b0), "r"(b1));
}

// ---------------------------------------------------------------------------
// fp32 -> bf16 hi/lo split (elementwise, float4 granularity)
// ---------------------------------------------------------------------------
__global__ __launch_bounds__(256) void convert_kernel(
    const float* __restrict__ src, __nv_bfloat16* __restrict__ hi,
    __nv_bfloat16* __restrict__ lo, int n4)
{
    int i = blockIdx.x * blockDim.x + threadIdx.x;
    if (i >= n4) return;
    float4 x = reinterpret_cast<const float4*>(src)[i];
    __nv_bfloat162 h0 = __float22bfloat162_rn(make_float2(x.x, x.y));
    __nv_bfloat162 h1 = __float22bfloat162_rn(make_float2(x.z, x.w));
    float2 hf0 = make_float2(__low2float(h0), __high2float(h0));
    float2 hf1 = make_float2(__low2float(h1), __high2float(h1));
    __nv_bfloat162 l0 = __float22bfloat162_rn(make_float2(x.x - hf0.x, x.y - hf0.y));
    __nv_bfloat162 l1 = __float22bfloat162_rn(make_float2(x.z - hf1.x, x.w - hf1.y));
    reinterpret_cast<__nv_bfloat162*>(hi)[2*i]   = h0;
    reinterpret_cast<__nv_bfloat162*>(hi)[2*i+1] = h1;
    reinterpret_cast<__nv_bfloat162*>(lo)[2*i]   = l0;
    reinterpret_cast<__nv_bfloat162*>(lo)[2*i+1] = l1;
}

// ---------------------------------------------------------------------------
// HMMA bf16-split GEMM: Y[n,j] = sum_d X[n,d]*W[j,d] + bias[j]
// 128x128 block tile, BK=32, 3-stage cp.async pipeline, 8 warps (2x4),
// warp tile 64x32 (4 m-tiles x 4 n-tiles of m16n8k16).
// Smem rows padded to 40 bf16 (80B) -> conflict-free ldmatrix.
// ---------------------------------------------------------------------------
#define BK 32
#define LDSS 40                       // bf16 elems per padded smem row
#define MATB (128*LDSS*2)             // 10240 B per matrix tile
#define STGB (4*MATB)                 // Ahi|Alo|Bhi|Blo per stage
#define GEMM_SMEM (3*STGB)            // 122880 B
#define NSTAGE 16                     // K=512 / BK

__global__ __launch_bounds__(256, 1) void gemm_mma_kernel(
    const __nv_bfloat16* __restrict__ Xhi, const __nv_bfloat16* __restrict__ Xlo,
    const __nv_bfloat16* __restrict__ Whi, const __nv_bfloat16* __restrict__ Wlo,
    const float* __restrict__ bq, const float* __restrict__ bk,
    const float* __restrict__ bv, float* __restrict__ Yall)
{
    extern __shared__ char smem[];
    const int z = blockIdx.z;
    const __nv_bfloat16* Ah = Xhi + (size_t)z * NROWS * DIM;
    const __nv_bfloat16* Al = Xlo + (size_t)z * NROWS * DIM;
    const __nv_bfloat16* Bh = Whi + (size_t)z * DIM * DIM;
    const __nv_bfloat16* Bl = Wlo + (size_t)z * DIM * DIM;
    const float* bias = (z == 0) ? bq : (z == 1) ? bk : bv;
    float* Y = Yall + (size_t)z * NROWS * DIM;

    const int bm = blockIdx.y * 128;
    const int bn = blockIdx.x * 128;
    const int tid = threadIdx.x;
    const int wid = tid >> 5, lane = tid & 31;
    const int wm = wid >> 2, wn = wid & 3;

    uint32_t sb = smem_u32(smem);

    // cp.async mapping: thread copies 32B (16 bf16) of row (tid>>1), k-half (tid&1)
    const int cr = tid >> 1;
    const int ck = (tid & 1) * 16;
    const __nv_bfloat16* gAh = Ah + (size_t)(bm + cr) * DIM + ck;
    const __nv_bfloat16* gAl = Al + (size_t)(bm + cr) * DIM + ck;
    const __nv_bfloat16* gBh = Bh + (size_t)(bn + cr) * DIM + ck;
    const __nv_bfloat16* gBl = Bl + (size_t)(bn + cr) * DIM + ck;
    const uint32_t srow = (uint32_t)(cr * LDSS + ck) * 2;   // byte offset in tile

#define ISSUE(stage, k0)                                             \
    {                                                                \
        uint32_t s0 = sb + (stage) * STGB + srow;                    \
        cp16(s0 + 0*MATB,      gAh + (k0));                          \
        cp16(s0 + 0*MATB + 16, gAh + (k0) + 8);                      \
        cp16(s0 + 1*MATB,      gAl + (k0));                          \
        cp16(s0 + 1*MATB + 16, gAl + (k0) + 8);                      \
        cp16(s0 + 2*MATB,      gBh + (k0));                          \
        cp16(s0 + 2*MATB + 16, gBh + (k0) + 8);                      \
        cp16(s0 + 3*MATB,      gBl + (k0));                          \
        cp16(s0 + 3*MATB + 16, gBl + (k0) + 8);                      \
        cp_commit();                                                 \
    }

    ISSUE(0, 0)
    ISSUE(1, BK)

    float acc[4][4][4];
#pragma unroll
    for (int i = 0; i < 4; i++)
#pragma unroll
        for (int j = 0; j < 4; j++)
#pragma unroll
            for (int r = 0; r < 4; r++) acc[i][j][r] = 0.f;

    const uint32_t lrow = lane & 15;            // ldmatrix row within 16
    const uint32_t lhalf = (lane >> 4) * 8;     // k column half

    for (int s = 0; s < NSTAGE; s++) {
        if (s < NSTAGE - 2) cp_wait<1>(); else cp_wait<0>();
        __syncthreads();
        uint32_t st = sb + (s % 3) * STGB;

#pragma unroll
        for (int ks = 0; ks < 2; ks++) {
            uint32_t ahi[4][4], alo[4][4], bhi[2][4], blo[2][4];
#pragma unroll
            for (int mt = 0; mt < 4; mt++) {
                uint32_t addr = st +
                    ((wm*64 + mt*16 + lrow) * LDSS + ks*16 + lhalf) * 2;
                ldsm4(ahi[mt], addr);
                ldsm4(alo[mt], addr + MATB);
            }
#pragma unroll
            for (int bt = 0; bt < 2; bt++) {
                uint32_t addr = st + 2*MATB +
                    ((wn*32 + bt*16 + lrow) * LDSS + ks*16 + lhalf) * 2;
                ldsm4(bhi[bt], addr);
                ldsm4(blo[bt], addr + MATB);
            }
#pragma unroll
            for (int mt = 0; mt < 4; mt++) {
#pragma unroll
                for (int nt = 0; nt < 4; nt++) {
                    int g = nt >> 1, o = nt & 1;   // even tile {r0,r2}, odd {r1,r3}
                    uint32_t bh0 = bhi[g][o], bh1 = bhi[g][o+2];
                    uint32_t bl0 = blo[g][o], bl1 = blo[g][o+2];
                    mma16816(acc[mt][nt], ahi[mt], bh0, bh1);
                    mma16816(acc[mt][nt], ahi[mt], bl0, bl1);
                    mma16816(acc[mt][nt], alo[mt], bh0, bh1);
                }
            }
        }
        if (s + 2 < NSTAGE) ISSUE((s + 2) % 3, (s + 2) * BK)
        __syncthreads();
    }
#undef ISSUE

    // Epilogue: bias add + store (d0,d1 -> row, d2,d3 -> row+8; col pairs)
#pragma unroll
    for (int nt = 0; nt < 4; nt++) {
        int col = bn + wn*32 + nt*8 + (lane & 3)*2;
        float2 b2 = make_float2(bias[col], bias[col+1]);
#pragma unroll
        for (int mt = 0; mt < 4; mt++) {
            int row = bm + wm*64 + mt*16 + (lane >> 2);
            float* y0 = Y + (size_t)row * DIM + col;
            float2 v0 = make_float2(acc[mt][nt][0] + b2.x, acc[mt][nt][1] + b2.y);
            float2 v1 = make_float2(acc[mt][nt][2] + b2.x, acc[mt][nt][3] + b2.y);
            *reinterpret_cast<float2*>(y0)            = v0;
            *reinterpret_cast<float2*>(y0 + 8 * DIM)  = v1;
        }
    }
}

// ---------------------------------------------------------------------------
// Lorentz transform: warp-per-row, 3 tensors fused via grid.y
// ---------------------------------------------------------------------------
__global__ __launch_bounds__(256) void lorentz_kernel(
    float* __restrict__ Yall,
    const float* __restrict__ lsq, const float* __restrict__ lsk,
    const float* __restrict__ lsv)
{
    const int z = blockIdx.y;
    float* Y = Yall + (size_t)z * NROWS * DIM;
    const float* ls = (z == 0) ? lsq : (z == 1) ? lsk : lsv;

    int row  = blockIdx.x * 8 + (threadIdx.x >> 5);
    int lane = threadIdx.x & 31;
    float* y = Y + (size_t)row * DIM + lane * 4;

    float4 v[4];
#pragma unroll
    for (int c = 0; c < 4; c++) v[c] = *reinterpret_cast<float4*>(y + c * 128);

    float ss = 0.f;
#pragma unroll
    for (int c = 0; c < 4; c++)
        ss += v[c].x*v[c].x + v[c].y*v[c].y + v[c].z*v[c].z + v[c].w*v[c].w;
    if (lane == 0) ss -= v[0].x * v[0].x;   // exclude time slot
#pragma unroll
    for (int o = 16; o > 0; o >>= 1) ss += __shfl_xor_sync(0xffffffffu, ss, o);

    float x0 = __shfl_sync(0xffffffffu, v[0].x, 0);
    float time = expf(ls[0]) / (1.f + expf(-x0)) + 1.0001f;
    float scale = sqrtf((time * time - 1.f) / fmaxf(ss, 1e-8f));
#pragma unroll
    for (int c = 0; c < 4; c++) {
        v[c].x *= scale; v[c].y *= scale; v[c].z *= scale; v[c].w *= scale;
    }
    if (lane == 0) v[0].x = time;
#pragma unroll
    for (int c = 0; c < 4; c++) *reinterpret_cast<float4*>(y + c * 128) = v[c];
}

// ---------------------------------------------------------------------------
// Per (b,h): CS[d] = (2/as + ab) * sum_s V[s,d]
// ---------------------------------------------------------------------------
__global__ __launch_bounds__(64) void colsum_kernel(
    const float* __restrict__ Vb, float* __restrict__ CS,
    const float* __restrict__ as_p, const float* __restrict__ ab_p)
{
    int bh = blockIdx.x;
    int b = bh >> 3, h = bh & 7;
    int d = threadIdx.x;
    const float* vp = Vb + (size_t)b * SEQ * DIM + h * DPH + d;
    float a0 = 0.f, a1 = 0.f, a2 = 0.f, a3 = 0.f;
#pragma unroll 4
    for (int s = 0; s < SEQ; s += 4) {
        a0 += vp[(size_t)(s+0) * DIM];
        a1 += vp[(size_t)(s+1) * DIM];
        a2 += vp[(size_t)(s+2) * DIM];
        a3 += vp[(size_t)(s+3) * DIM];
    }
    float c1 = 2.f / as_p[0] + ab_p[0];
    CS[bh * DPH + d] = (a0 + a1 + a2 + a3) * c1;
}

// ---------------------------------------------------------------------------
// Per (b,h): M'[d1,d2] = (2/as) * sgn[d1] * sum_s K[s,d1]*V[s,d2]
// ---------------------------------------------------------------------------
__global__ __launch_bounds__(256) void kkv_kernel(
    const float* __restrict__ Kb, const float* __restrict__ Vb,
    float* __restrict__ M, const float* __restrict__ as_p)
{
    int bh = blockIdx.x;
    int b = bh >> 3, h = bh & 7;
    __shared__ float Ks[32][64];
    __shared__ float Vs[32][64];
    int tid = threadIdx.x;
    int d1b = (tid >> 4) * 4;
    int d2b = (tid & 15) * 4;
    int lr = tid >> 3;
    int lc = (tid & 7) * 8;
    float acc[4][4];
#pragma unroll
    for (int i = 0; i < 4; i++)
#pragma unroll
        for (int j = 0; j < 4; j++) acc[i][j] = 0.f;

    const float* kp = Kb + (size_t)b * SEQ * DIM + h * DPH;
    const float* vp = Vb + (size_t)b * SEQ * DIM + h * DPH;

    for (int s0 = 0; s0 < SEQ; s0 += 32) {
        float4 k0 = *(const float4*)(kp + (size_t)(s0+lr) * DIM + lc);
        float4 k1 = *(const float4*)(kp + (size_t)(s0+lr) * DIM + lc + 4);
        float4 v0 = *(const float4*)(vp + (size_t)(s0+lr) * DIM + lc);
        float4 v1 = *(const float4*)(vp + (size_t)(s0+lr) * DIM + lc + 4);
        __syncthreads();
        *(float4*)&Ks[lr][lc]   = k0; *(float4*)&Ks[lr][lc+4] = k1;
        *(float4*)&Vs[lr][lc]   = v0; *(float4*)&Vs[lr][lc+4] = v1;
        __syncthreads();
#pragma unroll
        for (int ss = 0; ss < 32; ss++) {
            float4 kv = *(const float4*)&Ks[ss][d1b];
            float4 vv = *(const float4*)&Vs[ss][d2b];
            float ka[4] = {kv.x, kv.y, kv.z, kv.w};
            float va[4] = {vv.x, vv.y, vv.z, vv.w};
#pragma unroll
            for (int i = 0; i < 4; i++)
#pragma unroll
                for (int j = 0; j < 4; j++) acc[i][j] += ka[i] * va[j];
        }
    }

    float c2 = 2.f / as_p[0];
    float* Mp = M + (size_t)bh * DPH * DPH;
#pragma unroll
    for (int i = 0; i < 4; i++) {
        float sg = (d1b + i == 0) ? -c2 : c2;
#pragma unroll
        for (int j = 0; j < 4; j++)
            Mp[(d1b + i) * DPH + d2b + j] = acc[i][j] * sg;
    }
}

// ---------------------------------------------------------------------------
// ave[s,d] = CS[d] + sum_{d'} Q[s,d'] * M'[d',d]; normalize by Lorentz norm
// ---------------------------------------------------------------------------
__global__ __launch_bounds__(256) void ave_kernel(
    const float* __restrict__ Qb, const float* __restrict__ M,
    const float* __restrict__ CS, float* __restrict__ Out)
{
    int bh = blockIdx.x;
    int b = bh >> 3, h = bh & 7;
    int s0 = blockIdx.y * 32;
    int tid = threadIdx.x;
    int warp = tid >> 5, lane = tid & 31;

    __shared__ float Ms[64][64];
    {
        const float* Mp = M + (size_t)bh * DPH * DPH;
        float* Msf = &Ms[0][0];
        for (int i = tid * 4; i < 4096; i += 1024)
            *(float4*)&Msf[i] = *(const float4*)&Mp[i];
    }
    __syncthreads();

    float cs0 = CS[bh * DPH + lane];
    float cs1 = CS[bh * DPH + lane + 32];
    const float* qp = Qb + (size_t)b * SEQ * DIM + h * DPH;

    for (int r = warp; r < 32; r += 8) {
        int srow = s0 + r;
        const float* q = qp + (size_t)srow * DIM;
        float a0 = cs0, a1 = cs1;
#pragma unroll
        for (int dp = 0; dp < 64; dp++) {
            float qv = __ldg(&q[dp]);
            a0 += qv * Ms[dp][lane];
            a1 += qv * Ms[dp][lane + 32];
        }
        float contrib = a0 * a0 * ((lane == 0) ? -1.f : 1.f) + a1 * a1;
#pragma unroll
        for (int o = 16; o > 0; o >>= 1) contrib += __shfl_xor_sync(0xffffffffu, contrib, o);
        float inv = 1.f / sqrtf(fmaxf(fabsf(contrib), 1e-8f));
        size_t ob = ((size_t)b * SEQ + srow) * DIM + h * DPH;
        Out[ob + lane]      = a0 * inv;
        Out[ob + lane + 32] = a1 * inv;
    }
}

// ===========================================================================
extern "C" void kernel_launch(void* const* d_in, const int* in_sizes, int n_in,
                              void* d_out, int out_size)
{
    const float* key   = (const float*)d_in[0];
    const float* value = (const float*)d_in[1];
    const float* query = (const float*)d_in[2];
    const float* Wq  = (const float*)d_in[3];
    const float* bq  = (const float*)d_in[4];
    const float* lsq = (const float*)d_in[5];
    const float* Wk  = (const float*)d_in[6];
    const float* bk  = (const float*)d_in[7];
    const float* lsk = (const float*)d_in[8];
    const float* Wv  = (const float*)d_in[9];
    const float* bv  = (const float*)d_in[10];
    const float* lsv = (const float*)d_in[11];
    const float* as_p = (const float*)d_in[12];
    const float* ab_p = (const float*)d_in[13];
    float* out = (float*)d_out;

    float *gqkv, *gM, *gcs;
    __nv_bfloat16 *gxhi, *gxlo, *gwhi, *gwlo;
    cudaGetSymbolAddress((void**)&gqkv, g_qkv);
    cudaGetSymbolAddress((void**)&gxhi, g_xhi);
    cudaGetSymbolAddress((void**)&gxlo, g_xlo);
    cudaGetSymbolAddress((void**)&gwhi, g_whi);
    cudaGetSymbolAddress((void**)&gwlo, g_wlo);
    cudaGetSymbolAddress((void**)&gM,   g_M);
    cudaGetSymbolAddress((void**)&gcs,  g_cs);

    float* gq = gqkv;
    float* gk = gqkv + (size_t)NROWS * DIM;
    float* gv = gqkv + (size_t)2 * NROWS * DIM;

    // --- convert inputs to bf16 hi/lo ---
    const int XN4 = NROWS * DIM / 4;   // 2097152
    const int WN4 = DIM * DIM / 4;     // 65536
    convert_kernel<<<XN4/256, 256>>>(query, gxhi,                 gxlo,                 XN4);
    convert_kernel<<<XN4/256, 256>>>(key,   gxhi +   NROWS*DIM,   gxlo +   NROWS*DIM,   XN4);
    convert_kernel<<<XN4/256, 256>>>(value, gxhi + 2*NROWS*DIM,   gxlo + 2*NROWS*DIM,   XN4);
    convert_kernel<<<WN4/256, 256>>>(Wq,    gwhi,                 gwlo,                 WN4);
    convert_kernel<<<WN4/256, 256>>>(Wk,    gwhi +   DIM*DIM,     gwlo +   DIM*DIM,     WN4);
    convert_kernel<<<WN4/256, 256>>>(Wv,    gwhi + 2*DIM*DIM,     gwlo + 2*DIM*DIM,     WN4);

    // --- fused three GEMMs on tensor cores ---
    cudaFuncSetAttribute(gemm_mma_kernel,
                         cudaFuncAttributeMaxDynamicSharedMemorySize, GEMM_SMEM);
    dim3 ggrid(DIM / 128, NROWS / 128, 3);
    gemm_mma_kernel<<<ggrid, 256, GEMM_SMEM>>>(
        gxhi, gxlo, gwhi, gwlo, bq, bk, bv, gqkv);

    // --- Lorentz transforms (warp per row, 3 tensors) ---
    dim3 lgrid(NROWS / 8, 3);
    lorentz_kernel<<<lgrid, 256>>>(gqkv, lsq, lsk, lsv);

    colsum_kernel<<<BATCH * NHEAD, 64>>>(gv, gcs, as_p, ab_p);
    kkv_kernel<<<BATCH * NHEAD, 256>>>(gk, gv, gM, as_p);

    dim3 agrid(BATCH * NHEAD, SEQ / 32);
    ave_kernel<<<agrid, 256>>>(gq, gM, gcs, out);
}